// round 12
// baseline (speedup 1.0000x reference)
#include <cuda_runtime.h>
#include <cuda_bf16.h>
#include <math.h>
#include <stdint.h>

// Problem constants
#define Bsz  2
#define Ssz  2048
#define Dsz  1024
#define Hsz  16
#define DKsz 64
#define Mtot (Bsz * Ssz)   // 4096
#define Ntot Dsz           // 1024
#define Ktot Dsz           // 1024

// ---------------------------------------------------------------------------
// Scratch (device globals: allocation-free)
// ---------------------------------------------------------------------------
__device__ __nv_bfloat16 g_q_hi[Mtot * Ktot],  g_q_lo[Mtot * Ktot];
__device__ __nv_bfloat16 g_k_hi[Mtot * Ktot],  g_k_lo[Mtot * Ktot];
__device__ __nv_bfloat16 g_v_hi[Mtot * Ktot],  g_v_lo[Mtot * Ktot];
__device__ __nv_bfloat16 g_qh_hi[Mtot * Ktot], g_qh_lo[Mtot * Ktot];
__device__ __nv_bfloat16 g_kh_hi[Mtot * Ktot], g_kh_lo[Mtot * Ktot];
__device__ __nv_bfloat16 g_vh_hi[Mtot * Ktot], g_vh_lo[Mtot * Ktot];
__device__ __nv_bfloat16 g_att_hi[Mtot * Ktot], g_att_lo[Mtot * Ktot];
__device__ __nv_bfloat16 g_wq_hi[Dsz * Dsz], g_wq_lo[Dsz * Dsz];
__device__ __nv_bfloat16 g_wk_hi[Dsz * Dsz], g_wk_lo[Dsz * Dsz];
__device__ __nv_bfloat16 g_wv_hi[Dsz * Dsz], g_wv_lo[Dsz * Dsz];
__device__ __nv_bfloat16 g_wo_hi[Dsz * Dsz], g_wo_lo[Dsz * Dsz];

// ---------------------------------------------------------------------------
// Helpers
// ---------------------------------------------------------------------------
__device__ __forceinline__ uint32_t smem_to_u32(const void* smem_ptr) {
    uint32_t addr;
    asm("{ .reg .u64 tmp; cvta.to.shared.u64 tmp, %1; cvt.u32.u64 %0, tmp; }"
        : "=r"(addr) : "l"(smem_ptr));
    return addr;
}

__device__ __forceinline__ void cp_async16(uint32_t dst, const void* src) {
    asm volatile("cp.async.cg.shared.global [%0], [%1], 16;" :: "r"(dst), "l"(src));
}
__device__ __forceinline__ void cp_async_commit() {
    asm volatile("cp.async.commit_group;");
}
template <int N>
__device__ __forceinline__ void cp_async_wait() {
    asm volatile("cp.async.wait_group %0;" :: "n"(N));
}

__device__ __forceinline__ void ldsm_x4(uint32_t& r0, uint32_t& r1, uint32_t& r2,
                                        uint32_t& r3, uint32_t addr) {
    asm volatile("ldmatrix.sync.aligned.m8n8.x4.shared.b16 {%0,%1,%2,%3}, [%4];"
                 : "=r"(r0), "=r"(r1), "=r"(r2), "=r"(r3) : "r"(addr));
}
__device__ __forceinline__ void ldsm_x4_trans(uint32_t& r0, uint32_t& r1, uint32_t& r2,
                                              uint32_t& r3, uint32_t addr) {
    asm volatile("ldmatrix.sync.aligned.m8n8.x4.trans.shared.b16 {%0,%1,%2,%3}, [%4];"
                 : "=r"(r0), "=r"(r1), "=r"(r2), "=r"(r3) : "r"(addr));
}

__device__ __forceinline__ void mma16816(float* d,
                                         uint32_t a0, uint32_t a1, uint32_t a2, uint32_t a3,
                                         uint32_t b0, uint32_t b1) {
    asm volatile(
        "mma.sync.aligned.m16n8k16.row.col.f32.bf16.bf16.f32 "
        "{%0,%1,%2,%3}, {%4,%5,%6,%7}, {%8,%9}, {%0,%1,%2,%3};"
        : "+f"(d[0]), "+f"(d[1]), "+f"(d[2]), "+f"(d[3])
        : "r"(a0), "r"(a1), "r"(a2), "r"(a3), "r"(b0), "r"(b1));
}

__device__ __forceinline__ void split2(float x, float y, uint32_t& h, uint32_t& l) {
    __nv_bfloat162 hh = __floats2bfloat162_rn(x, y);
    float rx = x - __bfloat162float(hh.x);
    float ry = y - __bfloat162float(hh.y);
    __nv_bfloat162 ll = __floats2bfloat162_rn(rx, ry);
    h = *(uint32_t*)&hh;
    l = *(uint32_t*)&ll;
}

// ---------------------------------------------------------------------------
// fp32 -> (hi, lo) bf16 split
// ---------------------------------------------------------------------------
__global__ void split_kernel(const float* __restrict__ x,
                             __nv_bfloat16* __restrict__ hi,
                             __nv_bfloat16* __restrict__ lo, int n4)
{
    int i = blockIdx.x * blockDim.x + threadIdx.x;
    if (i >= n4) return;
    float4 v = ((const float4*)x)[i];
    uint32_t h0, l0, h1, l1;
    split2(v.x, v.y, h0, l0);
    split2(v.z, v.w, h1, l1);
    ((uint32_t*)hi)[i * 2 + 0] = h0;
    ((uint32_t*)hi)[i * 2 + 1] = h1;
    ((uint32_t*)lo)[i * 2 + 0] = l0;
    ((uint32_t*)lo)[i * 2 + 1] = l1;
}

// ---------------------------------------------------------------------------
// bf16x3 GEMM via mma.sync: out[M,N] = A[M,K] @ B[N,K]^T + bias
// CTA 128x128, BK=32, 8 warps, 3-stage cp.async pipeline.
// MODE 0: fp32 [M,N] output. MODE 1: bf16 hi/lo head-scatter output w/ scale.
// ---------------------------------------------------------------------------
#define BK 32
#define NC (Ktot / BK)                 // 32 chunks
#define TILE_B (128 * BK * 2)          // 8192 bytes per bf16 tile
#define BUF_B  (4 * TILE_B)            // Ahi, Alo, Bhi, Blo = 32 KB
#define NSTAGE 3
#define GEMM_SMEM (NSTAGE * BUF_B)     // 96 KB

__device__ __forceinline__ uint32_t sw_off(int row, int c) {
    return (uint32_t)(row * 64 + ((c ^ ((row >> 1) & 3)) << 4));
}

__device__ __forceinline__ void prefetch_chunk(
    uint32_t sbase, int buf,
    const __nv_bfloat16* Ahi, const __nv_bfloat16* Alo,
    const __nv_bfloat16* Bhi, const __nv_bfloat16* Blo,
    int bm, int bn, int k0, int tid)
{
    const __nv_bfloat16* srcs[4] = { Ahi, Alo, Bhi, Blo };
    const int r0[4] = { bm, bm, bn, bn };
    uint32_t base = sbase + buf * BUF_B;
#pragma unroll
    for (int t = 0; t < 4; t++) {
#pragma unroll
        for (int it = 0; it < 2; it++) {
            int seg = tid + it * 256;          // 0..511
            int row = seg >> 2;                // 0..127
            int c   = seg & 3;                 // 16B chunk
            const void* src = srcs[t] + (size_t)(r0[t] + row) * Ktot + k0 + c * 8;
            cp_async16(base + t * TILE_B + sw_off(row, c), src);
        }
    }
}

template <int MODE>
__global__ __launch_bounds__(256, 2) void gemm_tc_kernel(
    const __nv_bfloat16* __restrict__ Ahi, const __nv_bfloat16* __restrict__ Alo,
    const __nv_bfloat16* __restrict__ Bhi, const __nv_bfloat16* __restrict__ Blo,
    const float* __restrict__ bias, float* __restrict__ outF,
    __nv_bfloat16* __restrict__ outH, __nv_bfloat16* __restrict__ outL, float scale)
{
    extern __shared__ __align__(128) char smem[];
    const uint32_t sbase = smem_to_u32(smem);

    const int tid = threadIdx.x;
    const int wid = tid >> 5;
    const int lid = tid & 31;
    const int wr = wid >> 2;          // 0..1
    const int wc = wid & 3;           // 0..3
    const int bm = blockIdx.y * 128;
    const int bn = blockIdx.x * 128;

    float acc[4][4][4];
#pragma unroll
    for (int mi = 0; mi < 4; mi++)
#pragma unroll
        for (int ni = 0; ni < 4; ni++)
#pragma unroll
            for (int r = 0; r < 4; r++) acc[mi][ni][r] = 0.0f;

    prefetch_chunk(sbase, 0, Ahi, Alo, Bhi, Blo, bm, bn, 0, tid);
    cp_async_commit();
    prefetch_chunk(sbase, 1, Ahi, Alo, Bhi, Blo, bm, bn, BK, tid);
    cp_async_commit();

    int bufc = 0;
    for (int c = 0; c < NC; c++) {
        if (c + 2 < NC) {
            int nb = bufc + 2; if (nb >= NSTAGE) nb -= NSTAGE;
            prefetch_chunk(sbase, nb, Ahi, Alo, Bhi, Blo, bm, bn, (c + 2) * BK, tid);
            cp_async_commit();
            cp_async_wait<2>();
        } else if (c + 1 < NC) {
            cp_async_wait<1>();
        } else {
            cp_async_wait<0>();
        }
        __syncthreads();

        const uint32_t buf = sbase + bufc * BUF_B;
        const uint32_t sAhi = buf + 0 * TILE_B;
        const uint32_t sAlo = buf + 1 * TILE_B;
        const uint32_t sBhi = buf + 2 * TILE_B;
        const uint32_t sBlo = buf + 3 * TILE_B;

#pragma unroll
        for (int ks = 0; ks < 2; ks++) {
            uint32_t bh[4][2], bl[4][2];
#pragma unroll
            for (int p = 0; p < 2; p++) {
                const int nrow = wc * 32 + p * 16 + (lid & 15);
                const int kc = ks * 2 + (lid >> 4);
                uint32_t r0, r1, r2, r3;
                ldsm_x4(r0, r1, r2, r3, sBhi + sw_off(nrow, kc));
                bh[p * 2][0] = r0; bh[p * 2 + 1][0] = r1;
                bh[p * 2][1] = r2; bh[p * 2 + 1][1] = r3;
                ldsm_x4(r0, r1, r2, r3, sBlo + sw_off(nrow, kc));
                bl[p * 2][0] = r0; bl[p * 2 + 1][0] = r1;
                bl[p * 2][1] = r2; bl[p * 2 + 1][1] = r3;
            }
#pragma unroll
            for (int mi = 0; mi < 4; mi++) {
                const int mrow = wr * 64 + mi * 16 + (lid & 15);
                const int kc = ks * 2 + (lid >> 4);
                uint32_t ah0, ah1, ah2, ah3, al0, al1, al2, al3;
                ldsm_x4(ah0, ah1, ah2, ah3, sAhi + sw_off(mrow, kc));
                ldsm_x4(al0, al1, al2, al3, sAlo + sw_off(mrow, kc));
#pragma unroll
                for (int ni = 0; ni < 4; ni++) {
                    float* d = acc[mi][ni];
                    mma16816(d, ah0, ah1, ah2, ah3, bh[ni][0], bh[ni][1]);
                    mma16816(d, ah0, ah1, ah2, ah3, bl[ni][0], bl[ni][1]);
                    mma16816(d, al0, al1, al2, al3, bh[ni][0], bh[ni][1]);
                }
            }
        }
        __syncthreads();
        if (++bufc == NSTAGE) bufc = 0;
    }

#pragma unroll
    for (int mi = 0; mi < 4; mi++) {
#pragma unroll
        for (int ni = 0; ni < 4; ni++) {
#pragma unroll
            for (int half = 0; half < 2; half++) {
                const int m = bm + wr * 64 + mi * 16 + (lid >> 2) + half * 8;
                const int n = bn + wc * 32 + ni * 8 + 2 * (lid & 3);
                float v0 = acc[mi][ni][half * 2 + 0] + bias[n];
                float v1 = acc[mi][ni][half * 2 + 1] + bias[n + 1];
                if (MODE == 0) {
                    *(float2*)&outF[(size_t)m * Ntot + n] = make_float2(v0, v1);
                } else {
                    v0 *= scale; v1 *= scale;
                    uint32_t h, l;
                    split2(v0, v1, h, l);
                    const int b  = m >> 11;
                    const int s  = m & 2047;
                    const int hh = n >> 6;
                    const int dk = n & 63;
                    const size_t idx = (((size_t)(b * Hsz + hh) * Ssz) + s) * DKsz + dk;
                    *(uint32_t*)&outH[idx] = h;
                    *(uint32_t*)&outL[idx] = l;
                }
            }
        }
    }
}

// ---------------------------------------------------------------------------
// Flash attention via mma.sync bf16x3. Causal.
// 256 threads (8 warps), BQ=128 (16 rows/warp), BKV=64, DK=64.
// smem: Q hi/lo (32KB) + double-buffered K/V hi/lo (64KB) = 96KB.
// ---------------------------------------------------------------------------
#define FA_QTILE 16384                 // 128x64 bf16
#define FA_TILE  8192                  // 64x64 bf16
#define FA_KVBUF (4 * FA_TILE)         // KH, KL, VH, VL = 32KB
#define FA_SMEM (2 * FA_QTILE + 2 * FA_KVBUF)   // 96 KB

__device__ __forceinline__ uint32_t fa_sw(int row, int c) {
    return (uint32_t)(row * 128 + ((c ^ (row & 7)) << 4));
}

__device__ __forceinline__ void fa_prefetch_kv(
    uint32_t dstbase,
    const __nv_bfloat16* KH, const __nv_bfloat16* KL,
    const __nv_bfloat16* VH, const __nv_bfloat16* VL,
    size_t gbase, int tid)
{
    const __nv_bfloat16* srcs[4] = { KH, KL, VH, VL };
#pragma unroll
    for (int t = 0; t < 4; t++) {
#pragma unroll
        for (int it = 0; it < 2; it++) {
            int seg = tid + it * 256;      // 0..511
            int row = seg >> 3;
            int c   = seg & 7;
            cp_async16(dstbase + t * FA_TILE + fa_sw(row, c),
                       srcs[t] + gbase + (size_t)row * DKsz + c * 8);
        }
    }
}

__global__ __launch_bounds__(256, 2) void flash_mma_kernel(
    const __nv_bfloat16* __restrict__ QHI, const __nv_bfloat16* __restrict__ QLO,
    const __nv_bfloat16* __restrict__ KHI, const __nv_bfloat16* __restrict__ KLO,
    const __nv_bfloat16* __restrict__ VHI, const __nv_bfloat16* __restrict__ VLO,
    __nv_bfloat16* __restrict__ OHI, __nv_bfloat16* __restrict__ OLO)
{
    extern __shared__ __align__(128) char smem[];
    const uint32_t sb = smem_to_u32(smem);
    const int tid = threadIdx.x;
    const int wid = tid >> 5;
    const int lid = tid & 31;
    const int qi = gridDim.x - 1 - blockIdx.x;   // heavy tiles first
    const int bh = blockIdx.y;

    // ---- load Q hi/lo tiles (128 rows) ----
    const size_t qbase = ((size_t)bh * Ssz + qi * 128) * DKsz;
    {
        const __nv_bfloat16* srcs[2] = { QHI, QLO };
#pragma unroll
        for (int t = 0; t < 2; t++) {
#pragma unroll
            for (int it = 0; it < 4; it++) {
                int seg = tid + it * 256;   // 0..1023
                int row = seg >> 3;
                int c   = seg & 7;
                cp_async16(sb + t * FA_QTILE + fa_sw(row, c),
                           srcs[t] + qbase + (size_t)row * DKsz + c * 8);
            }
        }
    }
    cp_async_commit();
    const uint32_t kvbase = sb + 2 * FA_QTILE;
    fa_prefetch_kv(kvbase, KHI, KLO, VHI, VLO, ((size_t)bh * Ssz) * DKsz, tid);
    cp_async_commit();
    cp_async_wait<0>();
    __syncthreads();

    // ---- Q fragments (register resident), warp owns 16 rows ----
    uint32_t qfh[4][4], qfl[4][4];
#pragma unroll
    for (int t = 0; t < 4; t++) {
        const int row = wid * 16 + (lid & 15);
        const int c = t * 2 + (lid >> 4);
        const uint32_t off = fa_sw(row, c);
        ldsm_x4(qfh[t][0], qfh[t][1], qfh[t][2], qfh[t][3], sb + off);
        ldsm_x4(qfl[t][0], qfl[t][1], qfl[t][2], qfl[t][3], sb + FA_QTILE + off);
    }

    float o[8][4];
#pragma unroll
    for (int n = 0; n < 8; n++)
#pragma unroll
        for (int r = 0; r < 4; r++) o[n][r] = 0.0f;
    float mA = -INFINITY, mB = -INFINITY, lA = 0.0f, lB = 0.0f;

    const int rowA = qi * 128 + wid * 16 + (lid >> 2);
    const int rowB = rowA + 8;
    const int njt = 2 * qi + 2;                  // KV tiles in causal range

    for (int j = 0; j < njt; j++) {
        if (j + 1 < njt) {
            fa_prefetch_kv(kvbase + ((j + 1) & 1) * FA_KVBUF, KHI, KLO, VHI, VLO,
                           ((size_t)bh * Ssz + (j + 1) * 64) * DKsz, tid);
            cp_async_commit();
            cp_async_wait<1>();
        } else {
            cp_async_wait<0>();
        }
        __syncthreads();

        const uint32_t kb = kvbase + (j & 1) * FA_KVBUF;

        // ---- S = Q K^T (bf16x3) ----
        float s[8][4];
#pragma unroll
        for (int n = 0; n < 8; n++)
#pragma unroll
            for (int r = 0; r < 4; r++) s[n][r] = 0.0f;

#pragma unroll
        for (int t = 0; t < 4; t++) {
#pragma unroll
            for (int p = 0; p < 4; p++) {
                const int row = p * 16 + (lid & 15);
                const int c = t * 2 + (lid >> 4);
                const uint32_t off = fa_sw(row, c);
                uint32_t kh0, kh1, kh2, kh3, kl0, kl1, kl2, kl3;
                ldsm_x4(kh0, kh1, kh2, kh3, kb + off);
                ldsm_x4(kl0, kl1, kl2, kl3, kb + FA_TILE + off);
                mma16816(s[2 * p],     qfh[t][0], qfh[t][1], qfh[t][2], qfh[t][3], kh0, kh2);
                mma16816(s[2 * p + 1], qfh[t][0], qfh[t][1], qfh[t][2], qfh[t][3], kh1, kh3);
                mma16816(s[2 * p],     qfh[t][0], qfh[t][1], qfh[t][2], qfh[t][3], kl0, kl2);
                mma16816(s[2 * p + 1], qfh[t][0], qfh[t][1], qfh[t][2], qfh[t][3], kl1, kl3);
                mma16816(s[2 * p],     qfl[t][0], qfl[t][1], qfl[t][2], qfl[t][3], kh0, kh2);
                mma16816(s[2 * p + 1], qfl[t][0], qfl[t][1], qfl[t][2], qfl[t][3], kh1, kh3);
            }
        }

        // ---- causal mask (last two KV tiles overlap the diagonal) ----
        if (j >= 2 * qi) {
#pragma unroll
            for (int n = 0; n < 8; n++) {
                const int col = j * 64 + n * 8 + 2 * (lid & 3);
                if (col > rowA)     s[n][0] = -INFINITY;
                if (col + 1 > rowA) s[n][1] = -INFINITY;
                if (col > rowB)     s[n][2] = -INFINITY;
                if (col + 1 > rowB) s[n][3] = -INFINITY;
            }
        }

        // ---- online softmax ----
        float mxA = -INFINITY, mxB = -INFINITY;
#pragma unroll
        for (int n = 0; n < 8; n++) {
            mxA = fmaxf(mxA, fmaxf(s[n][0], s[n][1]));
            mxB = fmaxf(mxB, fmaxf(s[n][2], s[n][3]));
        }
        mxA = fmaxf(mxA, __shfl_xor_sync(0xffffffffu, mxA, 1));
        mxA = fmaxf(mxA, __shfl_xor_sync(0xffffffffu, mxA, 2));
        mxB = fmaxf(mxB, __shfl_xor_sync(0xffffffffu, mxB, 1));
        mxB = fmaxf(mxB, __shfl_xor_sync(0xffffffffu, mxB, 2));

        const float mnA = fmaxf(mA, mxA);
        const float mnB = fmaxf(mB, mxB);
        const float aA = __expf(mA - mnA);
        const float aB = __expf(mB - mnB);
        float sumA = 0.0f, sumB = 0.0f;
#pragma unroll
        for (int n = 0; n < 8; n++) {
            s[n][0] = __expf(s[n][0] - mnA);
            s[n][1] = __expf(s[n][1] - mnA);
            s[n][2] = __expf(s[n][2] - mnB);
            s[n][3] = __expf(s[n][3] - mnB);
            sumA += s[n][0] + s[n][1];
            sumB += s[n][2] + s[n][3];
        }
        sumA += __shfl_xor_sync(0xffffffffu, sumA, 1);
        sumA += __shfl_xor_sync(0xffffffffu, sumA, 2);
        sumB += __shfl_xor_sync(0xffffffffu, sumB, 1);
        sumB += __shfl_xor_sync(0xffffffffu, sumB, 2);
        lA = lA * aA + sumA;
        lB = lB * aB + sumB;
        mA = mnA; mB = mnB;
#pragma unroll
        for (int n = 0; n < 8; n++) {
            o[n][0] *= aA; o[n][1] *= aA;
            o[n][2] *= aB; o[n][3] *= aB;
        }

        // ---- O += P V (bf16x3) ----
#pragma unroll
        for (int t = 0; t < 4; t++) {
            uint32_t ph[4], pl[4];
            split2(s[2 * t][0],     s[2 * t][1],     ph[0], pl[0]);
            split2(s[2 * t][2],     s[2 * t][3],     ph[1], pl[1]);
            split2(s[2 * t + 1][0], s[2 * t + 1][1], ph[2], pl[2]);
            split2(s[2 * t + 1][2], s[2 * t + 1][3], ph[3], pl[3]);
#pragma unroll
            for (int dp = 0; dp < 4; dp++) {
                const int row = t * 16 + (lid & 15);
                const int c = dp * 2 + (lid >> 4);
                const uint32_t off = fa_sw(row, c);
                uint32_t vh0, vh1, vh2, vh3, vl0, vl1, vl2, vl3;
                ldsm_x4_trans(vh0, vh1, vh2, vh3, kb + 2 * FA_TILE + off);
                ldsm_x4_trans(vl0, vl1, vl2, vl3, kb + 3 * FA_TILE + off);
                mma16816(o[2 * dp],     ph[0], ph[1], ph[2], ph[3], vh0, vh1);
                mma16816(o[2 * dp + 1], ph[0], ph[1], ph[2], ph[3], vh2, vh3);
                mma16816(o[2 * dp],     ph[0], ph[1], ph[2], ph[3], vl0, vl1);
                mma16816(o[2 * dp + 1], ph[0], ph[1], ph[2], ph[3], vl2, vl3);
                mma16816(o[2 * dp],     pl[0], pl[1], pl[2], pl[3], vh0, vh1);
                mma16816(o[2 * dp + 1], pl[0], pl[1], pl[2], pl[3], vh2, vh3);
            }
        }
        __syncthreads();
    }

    // ---- epilogue ----
    const float invA = 1.0f / lA;
    const float invB = 1.0f / lB;
    const int b = bh >> 4;
    const int h = bh & 15;
    const int sA = qi * 128 + wid * 16 + (lid >> 2);
#pragma unroll
    for (int n = 0; n < 8; n++) {
        const int col = h * DKsz + n * 8 + 2 * (lid & 3);
        uint32_t hi0, lo0, hi1, lo1;
        split2(o[n][0] * invA, o[n][1] * invA, hi0, lo0);
        split2(o[n][2] * invB, o[n][3] * invB, hi1, lo1);
        const size_t iA = ((size_t)b * Ssz + sA) * Dsz + col;
        const size_t iB = ((size_t)b * Ssz + sA + 8) * Dsz + col;
        *(uint32_t*)&OHI[iA] = hi0;  *(uint32_t*)&OLO[iA] = lo0;
        *(uint32_t*)&OHI[iB] = hi1;  *(uint32_t*)&OLO[iB] = lo1;
    }
}

// ---------------------------------------------------------------------------
extern "C" void kernel_launch(void* const* d_in, const int* in_sizes, int n_in,
                              void* d_out, int out_size)
{
    const float* q   = (const float*)d_in[0];
    const float* k   = (const float*)d_in[1];
    const float* v   = (const float*)d_in[2];
    // d_in[3] = mask (causal, handled analytically)
    const float* w_q = (const float*)d_in[4];
    const float* b_q = (const float*)d_in[5];
    const float* w_k = (const float*)d_in[6];
    const float* b_k = (const float*)d_in[7];
    const float* w_v = (const float*)d_in[8];
    const float* b_v = (const float*)d_in[9];
    const float* w_o = (const float*)d_in[10];
    const float* b_o = (const float*)d_in[11];
    float* out = (float*)d_out;

    __nv_bfloat16 *qhi, *qlo, *khi, *klo, *vhi, *vlo;
    __nv_bfloat16 *qhh, *qhl, *khh, *khl, *vhh, *vhl, *ahi, *alo;
    __nv_bfloat16 *wqh, *wql, *wkh, *wkl, *wvh, *wvl, *woh, *wol;
    cudaGetSymbolAddress((void**)&qhi, g_q_hi);   cudaGetSymbolAddress((void**)&qlo, g_q_lo);
    cudaGetSymbolAddress((void**)&khi, g_k_hi);   cudaGetSymbolAddress((void**)&klo, g_k_lo);
    cudaGetSymbolAddress((void**)&vhi, g_v_hi);   cudaGetSymbolAddress((void**)&vlo, g_v_lo);
    cudaGetSymbolAddress((void**)&qhh, g_qh_hi);  cudaGetSymbolAddress((void**)&qhl, g_qh_lo);
    cudaGetSymbolAddress((void**)&khh, g_kh_hi);  cudaGetSymbolAddress((void**)&khl, g_kh_lo);
    cudaGetSymbolAddress((void**)&vhh, g_vh_hi);  cudaGetSymbolAddress((void**)&vhl, g_vh_lo);
    cudaGetSymbolAddress((void**)&ahi, g_att_hi); cudaGetSymbolAddress((void**)&alo, g_att_lo);
    cudaGetSymbolAddress((void**)&wqh, g_wq_hi);  cudaGetSymbolAddress((void**)&wql, g_wq_lo);
    cudaGetSymbolAddress((void**)&wkh, g_wk_hi);  cudaGetSymbolAddress((void**)&wkl, g_wk_lo);
    cudaGetSymbolAddress((void**)&wvh, g_wv_hi);  cudaGetSymbolAddress((void**)&wvl, g_wv_lo);
    cudaGetSymbolAddress((void**)&woh, g_wo_hi);  cudaGetSymbolAddress((void**)&wol, g_wo_lo);

    cudaFuncSetAttribute(gemm_tc_kernel<0>,
                         cudaFuncAttributeMaxDynamicSharedMemorySize, GEMM_SMEM);
    cudaFuncSetAttribute(gemm_tc_kernel<1>,
                         cudaFuncAttributeMaxDynamicSharedMemorySize, GEMM_SMEM);
    cudaFuncSetAttribute(flash_mma_kernel,
                         cudaFuncAttributeMaxDynamicSharedMemorySize, FA_SMEM);

    const int nAct = Mtot * Ktot;   // 4M
    const int nW   = Dsz * Dsz;     // 1M
    dim3 bSplit(256);
    dim3 gAct((nAct / 4 + 255) / 256);
    dim3 gW((nW / 4 + 255) / 256);

    split_kernel<<<gAct, bSplit>>>(q, qhi, qlo, nAct / 4);
    split_kernel<<<gAct, bSplit>>>(k, khi, klo, nAct / 4);
    split_kernel<<<gAct, bSplit>>>(v, vhi, vlo, nAct / 4);
    split_kernel<<<gW, bSplit>>>(w_q, wqh, wql, nW / 4);
    split_kernel<<<gW, bSplit>>>(w_k, wkh, wkl, nW / 4);
    split_kernel<<<gW, bSplit>>>(w_v, wvh, wvl, nW / 4);
    split_kernel<<<gW, bSplit>>>(w_o, woh, wol, nW / 4);

    dim3 gGemm(Ntot / 128, Mtot / 128);  // (8, 32)
    gemm_tc_kernel<1><<<gGemm, 256, GEMM_SMEM>>>(qhi, qlo, wqh, wql, b_q,
                                                 nullptr, qhh, qhl, 0.125f);
    gemm_tc_kernel<1><<<gGemm, 256, GEMM_SMEM>>>(khi, klo, wkh, wkl, b_k,
                                                 nullptr, khh, khl, 1.0f);
    gemm_tc_kernel<1><<<gGemm, 256, GEMM_SMEM>>>(vhi, vlo, wvh, wvl, b_v,
                                                 nullptr, vhh, vhl, 1.0f);

    dim3 gFlash(Ssz / 128, Bsz * Hsz);   // (16, 32)
    flash_mma_kernel<<<gFlash, 256, FA_SMEM>>>(qhh, qhl, khh, khl, vhh, vhl, ahi, alo);

    gemm_tc_kernel<0><<<gGemm, 256, GEMM_SMEM>>>(ahi, alo, woh, wol, b_o,
                                                 out, nullptr, nullptr, 1.0f);
}

// round 13
// speedup vs baseline: 1.0817x; 1.0817x over previous
#include <cuda_runtime.h>
#include <cuda_bf16.h>
#include <math.h>
#include <stdint.h>

// Problem constants
#define Bsz  2
#define Ssz  2048
#define Dsz  1024
#define Hsz  16
#define DKsz 64
#define Mtot (Bsz * Ssz)   // 4096
#define Ntot Dsz           // 1024
#define Ktot Dsz           // 1024

// ---------------------------------------------------------------------------
// Scratch (device globals: allocation-free)
// ---------------------------------------------------------------------------
__device__ __nv_bfloat16 g_q_hi[Mtot * Ktot],  g_q_lo[Mtot * Ktot];
__device__ __nv_bfloat16 g_k_hi[Mtot * Ktot],  g_k_lo[Mtot * Ktot];
__device__ __nv_bfloat16 g_v_hi[Mtot * Ktot],  g_v_lo[Mtot * Ktot];
__device__ __nv_bfloat16 g_qh_hi[Mtot * Ktot], g_qh_lo[Mtot * Ktot];
__device__ __nv_bfloat16 g_kh_hi[Mtot * Ktot], g_kh_lo[Mtot * Ktot];
__device__ __nv_bfloat16 g_vh_hi[Mtot * Ktot], g_vh_lo[Mtot * Ktot];
__device__ __nv_bfloat16 g_att_hi[Mtot * Ktot], g_att_lo[Mtot * Ktot];
__device__ __nv_bfloat16 g_wq_hi[Dsz * Dsz], g_wq_lo[Dsz * Dsz];
__device__ __nv_bfloat16 g_wk_hi[Dsz * Dsz], g_wk_lo[Dsz * Dsz];
__device__ __nv_bfloat16 g_wv_hi[Dsz * Dsz], g_wv_lo[Dsz * Dsz];
__device__ __nv_bfloat16 g_wo_hi[Dsz * Dsz], g_wo_lo[Dsz * Dsz];

// ---------------------------------------------------------------------------
// Helpers
// ---------------------------------------------------------------------------
__device__ __forceinline__ uint32_t smem_to_u32(const void* smem_ptr) {
    uint32_t addr;
    asm("{ .reg .u64 tmp; cvta.to.shared.u64 tmp, %1; cvt.u32.u64 %0, tmp; }"
        : "=r"(addr) : "l"(smem_ptr));
    return addr;
}

__device__ __forceinline__ void cp_async16(uint32_t dst, const void* src) {
    asm volatile("cp.async.cg.shared.global [%0], [%1], 16;" :: "r"(dst), "l"(src));
}
__device__ __forceinline__ void cp_async_commit() {
    asm volatile("cp.async.commit_group;");
}
template <int N>
__device__ __forceinline__ void cp_async_wait() {
    asm volatile("cp.async.wait_group %0;" :: "n"(N));
}

__device__ __forceinline__ void ldsm_x4(uint32_t& r0, uint32_t& r1, uint32_t& r2,
                                        uint32_t& r3, uint32_t addr) {
    asm volatile("ldmatrix.sync.aligned.m8n8.x4.shared.b16 {%0,%1,%2,%3}, [%4];"
                 : "=r"(r0), "=r"(r1), "=r"(r2), "=r"(r3) : "r"(addr));
}
__device__ __forceinline__ void ldsm_x4_trans(uint32_t& r0, uint32_t& r1, uint32_t& r2,
                                              uint32_t& r3, uint32_t addr) {
    asm volatile("ldmatrix.sync.aligned.m8n8.x4.trans.shared.b16 {%0,%1,%2,%3}, [%4];"
                 : "=r"(r0), "=r"(r1), "=r"(r2), "=r"(r3) : "r"(addr));
}

__device__ __forceinline__ void mma16816(float* d,
                                         uint32_t a0, uint32_t a1, uint32_t a2, uint32_t a3,
                                         uint32_t b0, uint32_t b1) {
    asm volatile(
        "mma.sync.aligned.m16n8k16.row.col.f32.bf16.bf16.f32 "
        "{%0,%1,%2,%3}, {%4,%5,%6,%7}, {%8,%9}, {%0,%1,%2,%3};"
        : "+f"(d[0]), "+f"(d[1]), "+f"(d[2]), "+f"(d[3])
        : "r"(a0), "r"(a1), "r"(a2), "r"(a3), "r"(b0), "r"(b1));
}

__device__ __forceinline__ void split2(float x, float y, uint32_t& h, uint32_t& l) {
    __nv_bfloat162 hh = __floats2bfloat162_rn(x, y);
    float rx = x - __bfloat162float(hh.x);
    float ry = y - __bfloat162float(hh.y);
    __nv_bfloat162 ll = __floats2bfloat162_rn(rx, ry);
    h = *(uint32_t*)&hh;
    l = *(uint32_t*)&ll;
}

// ---------------------------------------------------------------------------
// fp32 -> (hi, lo) bf16 split
// ---------------------------------------------------------------------------
__global__ void split_kernel(const float* __restrict__ x,
                             __nv_bfloat16* __restrict__ hi,
                             __nv_bfloat16* __restrict__ lo, int n4)
{
    int i = blockIdx.x * blockDim.x + threadIdx.x;
    if (i >= n4) return;
    float4 v = ((const float4*)x)[i];
    uint32_t h0, l0, h1, l1;
    split2(v.x, v.y, h0, l0);
    split2(v.z, v.w, h1, l1);
    ((uint32_t*)hi)[i * 2 + 0] = h0;
    ((uint32_t*)hi)[i * 2 + 1] = h1;
    ((uint32_t*)lo)[i * 2 + 0] = l0;
    ((uint32_t*)lo)[i * 2 + 1] = l1;
}

// ---------------------------------------------------------------------------
// bf16x3 GEMM via mma.sync: out[M,N] = A[M,K] @ B[N,K]^T + bias
// CTA 128x128, BK=32, 8 warps, 3-stage cp.async pipeline.
// MODE 0: fp32 [M,N] output. MODE 1: bf16 hi/lo head-scatter output w/ scale.
// ---------------------------------------------------------------------------
#define BK 32
#define NC (Ktot / BK)                 // 32 chunks
#define TILE_B (128 * BK * 2)          // 8192 bytes per bf16 tile
#define BUF_B  (4 * TILE_B)            // Ahi, Alo, Bhi, Blo = 32 KB
#define NSTAGE 3
#define GEMM_SMEM (NSTAGE * BUF_B)     // 96 KB

__device__ __forceinline__ uint32_t sw_off(int row, int c) {
    return (uint32_t)(row * 64 + ((c ^ ((row >> 1) & 3)) << 4));
}

__device__ __forceinline__ void prefetch_chunk(
    uint32_t sbase, int buf,
    const __nv_bfloat16* Ahi, const __nv_bfloat16* Alo,
    const __nv_bfloat16* Bhi, const __nv_bfloat16* Blo,
    int bm, int bn, int k0, int tid)
{
    const __nv_bfloat16* srcs[4] = { Ahi, Alo, Bhi, Blo };
    const int r0[4] = { bm, bm, bn, bn };
    uint32_t base = sbase + buf * BUF_B;
#pragma unroll
    for (int t = 0; t < 4; t++) {
#pragma unroll
        for (int it = 0; it < 2; it++) {
            int seg = tid + it * 256;          // 0..511
            int row = seg >> 2;                // 0..127
            int c   = seg & 3;                 // 16B chunk
            const void* src = srcs[t] + (size_t)(r0[t] + row) * Ktot + k0 + c * 8;
            cp_async16(base + t * TILE_B + sw_off(row, c), src);
        }
    }
}

template <int MODE>
__global__ __launch_bounds__(256, 2) void gemm_tc_kernel(
    const __nv_bfloat16* __restrict__ Ahi, const __nv_bfloat16* __restrict__ Alo,
    const __nv_bfloat16* __restrict__ Bhi, const __nv_bfloat16* __restrict__ Blo,
    const float* __restrict__ bias, float* __restrict__ outF,
    __nv_bfloat16* __restrict__ outH, __nv_bfloat16* __restrict__ outL, float scale)
{
    extern __shared__ __align__(128) char smem[];
    const uint32_t sbase = smem_to_u32(smem);

    const int tid = threadIdx.x;
    const int wid = tid >> 5;
    const int lid = tid & 31;
    const int wr = wid >> 2;          // 0..1
    const int wc = wid & 3;           // 0..3
    const int bm = blockIdx.y * 128;
    const int bn = blockIdx.x * 128;

    float acc[4][4][4];
#pragma unroll
    for (int mi = 0; mi < 4; mi++)
#pragma unroll
        for (int ni = 0; ni < 4; ni++)
#pragma unroll
            for (int r = 0; r < 4; r++) acc[mi][ni][r] = 0.0f;

    prefetch_chunk(sbase, 0, Ahi, Alo, Bhi, Blo, bm, bn, 0, tid);
    cp_async_commit();
    prefetch_chunk(sbase, 1, Ahi, Alo, Bhi, Blo, bm, bn, BK, tid);
    cp_async_commit();

    int bufc = 0;
    for (int c = 0; c < NC; c++) {
        if (c + 2 < NC) {
            int nb = bufc + 2; if (nb >= NSTAGE) nb -= NSTAGE;
            prefetch_chunk(sbase, nb, Ahi, Alo, Bhi, Blo, bm, bn, (c + 2) * BK, tid);
            cp_async_commit();
            cp_async_wait<2>();
        } else if (c + 1 < NC) {
            cp_async_wait<1>();
        } else {
            cp_async_wait<0>();
        }
        __syncthreads();

        const uint32_t buf = sbase + bufc * BUF_B;
        const uint32_t sAhi = buf + 0 * TILE_B;
        const uint32_t sAlo = buf + 1 * TILE_B;
        const uint32_t sBhi = buf + 2 * TILE_B;
        const uint32_t sBlo = buf + 3 * TILE_B;

#pragma unroll
        for (int ks = 0; ks < 2; ks++) {
            uint32_t bh[4][2], bl[4][2];
#pragma unroll
            for (int p = 0; p < 2; p++) {
                const int nrow = wc * 32 + p * 16 + (lid & 15);
                const int kc = ks * 2 + (lid >> 4);
                uint32_t r0, r1, r2, r3;
                ldsm_x4(r0, r1, r2, r3, sBhi + sw_off(nrow, kc));
                bh[p * 2][0] = r0; bh[p * 2 + 1][0] = r1;
                bh[p * 2][1] = r2; bh[p * 2 + 1][1] = r3;
                ldsm_x4(r0, r1, r2, r3, sBlo + sw_off(nrow, kc));
                bl[p * 2][0] = r0; bl[p * 2 + 1][0] = r1;
                bl[p * 2][1] = r2; bl[p * 2 + 1][1] = r3;
            }
#pragma unroll
            for (int mi = 0; mi < 4; mi++) {
                const int mrow = wr * 64 + mi * 16 + (lid & 15);
                const int kc = ks * 2 + (lid >> 4);
                uint32_t ah0, ah1, ah2, ah3, al0, al1, al2, al3;
                ldsm_x4(ah0, ah1, ah2, ah3, sAhi + sw_off(mrow, kc));
                ldsm_x4(al0, al1, al2, al3, sAlo + sw_off(mrow, kc));
#pragma unroll
                for (int ni = 0; ni < 4; ni++) {
                    float* d = acc[mi][ni];
                    mma16816(d, ah0, ah1, ah2, ah3, bh[ni][0], bh[ni][1]);
                    mma16816(d, ah0, ah1, ah2, ah3, bl[ni][0], bl[ni][1]);
                    mma16816(d, al0, al1, al2, al3, bh[ni][0], bh[ni][1]);
                }
            }
        }
        __syncthreads();
        if (++bufc == NSTAGE) bufc = 0;
    }

#pragma unroll
    for (int mi = 0; mi < 4; mi++) {
#pragma unroll
        for (int ni = 0; ni < 4; ni++) {
#pragma unroll
            for (int half = 0; half < 2; half++) {
                const int m = bm + wr * 64 + mi * 16 + (lid >> 2) + half * 8;
                const int n = bn + wc * 32 + ni * 8 + 2 * (lid & 3);
                float v0 = acc[mi][ni][half * 2 + 0] + bias[n];
                float v1 = acc[mi][ni][half * 2 + 1] + bias[n + 1];
                if (MODE == 0) {
                    *(float2*)&outF[(size_t)m * Ntot + n] = make_float2(v0, v1);
                } else {
                    v0 *= scale; v1 *= scale;
                    uint32_t h, l;
                    split2(v0, v1, h, l);
                    const int b  = m >> 11;
                    const int s  = m & 2047;
                    const int hh = n >> 6;
                    const int dk = n & 63;
                    const size_t idx = (((size_t)(b * Hsz + hh) * Ssz) + s) * DKsz + dk;
                    *(uint32_t*)&outH[idx] = h;
                    *(uint32_t*)&outL[idx] = l;
                }
            }
        }
    }
}

// ---------------------------------------------------------------------------
// Flash attention via mma.sync bf16x3. Causal.  (R9 config: 128 thr, BQ=64)
// smem: Q hi/lo (16KB) + double-buffered K/V hi/lo (64KB) = 80KB.
// ---------------------------------------------------------------------------
#define FA_TILE 8192                   // one 64x64 bf16 tile
#define FA_KVBUF (4 * FA_TILE)         // KH, KL, VH, VL
#define FA_SMEM (2 * FA_TILE + 2 * FA_KVBUF)   // 80 KB

__device__ __forceinline__ uint32_t fa_sw(int row, int c) {
    return (uint32_t)(row * 128 + ((c ^ (row & 7)) << 4));
}

__device__ __forceinline__ void fa_prefetch_kv(
    uint32_t dstbase,
    const __nv_bfloat16* KH, const __nv_bfloat16* KL,
    const __nv_bfloat16* VH, const __nv_bfloat16* VL,
    size_t gbase, int tid)
{
    const __nv_bfloat16* srcs[4] = { KH, KL, VH, VL };
#pragma unroll
    for (int t = 0; t < 4; t++) {
#pragma unroll
        for (int it = 0; it < 4; it++) {
            int seg = tid + it * 128;      // 0..511
            int row = seg >> 3;
            int c   = seg & 7;
            cp_async16(dstbase + t * FA_TILE + fa_sw(row, c),
                       srcs[t] + gbase + (size_t)row * DKsz + c * 8);
        }
    }
}

__global__ __launch_bounds__(128, 2) void flash_mma_kernel(
    const __nv_bfloat16* __restrict__ QHI, const __nv_bfloat16* __restrict__ QLO,
    const __nv_bfloat16* __restrict__ KHI, const __nv_bfloat16* __restrict__ KLO,
    const __nv_bfloat16* __restrict__ VHI, const __nv_bfloat16* __restrict__ VLO,
    __nv_bfloat16* __restrict__ OHI, __nv_bfloat16* __restrict__ OLO)
{
    extern __shared__ __align__(128) char smem[];
    const uint32_t sb = smem_to_u32(smem);
    const int tid = threadIdx.x;
    const int wid = tid >> 5;
    const int lid = tid & 31;
    const int qi = gridDim.x - 1 - blockIdx.x;   // heavy tiles first
    const int bh = blockIdx.y;

    // ---- load Q hi/lo tiles ----
    const size_t qbase = ((size_t)bh * Ssz + qi * 64) * DKsz;
    {
        const __nv_bfloat16* srcs[2] = { QHI, QLO };
#pragma unroll
        for (int t = 0; t < 2; t++) {
#pragma unroll
            for (int it = 0; it < 4; it++) {
                int seg = tid + it * 128;
                int row = seg >> 3;
                int c   = seg & 7;
                cp_async16(sb + t * FA_TILE + fa_sw(row, c),
                           srcs[t] + qbase + (size_t)row * DKsz + c * 8);
            }
        }
    }
    cp_async_commit();
    const uint32_t kvbase = sb + 2 * FA_TILE;
    fa_prefetch_kv(kvbase, KHI, KLO, VHI, VLO, ((size_t)bh * Ssz) * DKsz, tid);
    cp_async_commit();
    cp_async_wait<0>();
    __syncthreads();

    // ---- Q fragments (register resident) ----
    uint32_t qfh[4][4], qfl[4][4];
#pragma unroll
    for (int t = 0; t < 4; t++) {
        const int row = wid * 16 + (lid & 15);
        const int c = t * 2 + (lid >> 4);
        const uint32_t off = fa_sw(row, c);
        ldsm_x4(qfh[t][0], qfh[t][1], qfh[t][2], qfh[t][3], sb + off);
        ldsm_x4(qfl[t][0], qfl[t][1], qfl[t][2], qfl[t][3], sb + FA_TILE + off);
    }

    float o[8][4];
#pragma unroll
    for (int n = 0; n < 8; n++)
#pragma unroll
        for (int r = 0; r < 4; r++) o[n][r] = 0.0f;
    float mA = -INFINITY, mB = -INFINITY, lA = 0.0f, lB = 0.0f;

    const int rowA = qi * 64 + wid * 16 + (lid >> 2);
    const int rowB = rowA + 8;

    for (int j = 0; j <= qi; j++) {
        if (j < qi) {
            fa_prefetch_kv(kvbase + ((j + 1) & 1) * FA_KVBUF, KHI, KLO, VHI, VLO,
                           ((size_t)bh * Ssz + (j + 1) * 64) * DKsz, tid);
            cp_async_commit();
            cp_async_wait<1>();
        } else {
            cp_async_wait<0>();
        }
        __syncthreads();

        const uint32_t kb = kvbase + (j & 1) * FA_KVBUF;

        // ---- S = Q K^T (bf16x3) ----
        float s[8][4];
#pragma unroll
        for (int n = 0; n < 8; n++)
#pragma unroll
            for (int r = 0; r < 4; r++) s[n][r] = 0.0f;

#pragma unroll
        for (int t = 0; t < 4; t++) {
#pragma unroll
            for (int p = 0; p < 4; p++) {
                const int row = p * 16 + (lid & 15);
                const int c = t * 2 + (lid >> 4);
                const uint32_t off = fa_sw(row, c);
                uint32_t kh0, kh1, kh2, kh3, kl0, kl1, kl2, kl3;
                ldsm_x4(kh0, kh1, kh2, kh3, kb + off);
                ldsm_x4(kl0, kl1, kl2, kl3, kb + FA_TILE + off);
                mma16816(s[2 * p],     qfh[t][0], qfh[t][1], qfh[t][2], qfh[t][3], kh0, kh2);
                mma16816(s[2 * p + 1], qfh[t][0], qfh[t][1], qfh[t][2], qfh[t][3], kh1, kh3);
                mma16816(s[2 * p],     qfh[t][0], qfh[t][1], qfh[t][2], qfh[t][3], kl0, kl2);
                mma16816(s[2 * p + 1], qfh[t][0], qfh[t][1], qfh[t][2], qfh[t][3], kl1, kl3);
                mma16816(s[2 * p],     qfl[t][0], qfl[t][1], qfl[t][2], qfl[t][3], kh0, kh2);
                mma16816(s[2 * p + 1], qfl[t][0], qfl[t][1], qfl[t][2], qfl[t][3], kh1, kh3);
            }
        }

        // ---- causal mask (diagonal block only) ----
        if (j == qi) {
#pragma unroll
            for (int n = 0; n < 8; n++) {
                const int col = qi * 64 + n * 8 + 2 * (lid & 3);
                if (col > rowA)     s[n][0] = -INFINITY;
                if (col + 1 > rowA) s[n][1] = -INFINITY;
                if (col > rowB)     s[n][2] = -INFINITY;
                if (col + 1 > rowB) s[n][3] = -INFINITY;
            }
        }

        // ---- online softmax ----
        float mxA = -INFINITY, mxB = -INFINITY;
#pragma unroll
        for (int n = 0; n < 8; n++) {
            mxA = fmaxf(mxA, fmaxf(s[n][0], s[n][1]));
            mxB = fmaxf(mxB, fmaxf(s[n][2], s[n][3]));
        }
        mxA = fmaxf(mxA, __shfl_xor_sync(0xffffffffu, mxA, 1));
        mxA = fmaxf(mxA, __shfl_xor_sync(0xffffffffu, mxA, 2));
        mxB = fmaxf(mxB, __shfl_xor_sync(0xffffffffu, mxB, 1));
        mxB = fmaxf(mxB, __shfl_xor_sync(0xffffffffu, mxB, 2));

        const float mnA = fmaxf(mA, mxA);
        const float mnB = fmaxf(mB, mxB);
        const float aA = __expf(mA - mnA);
        const float aB = __expf(mB - mnB);
        float sumA = 0.0f, sumB = 0.0f;
#pragma unroll
        for (int n = 0; n < 8; n++) {
            s[n][0] = __expf(s[n][0] - mnA);
            s[n][1] = __expf(s[n][1] - mnA);
            s[n][2] = __expf(s[n][2] - mnB);
            s[n][3] = __expf(s[n][3] - mnB);
            sumA += s[n][0] + s[n][1];
            sumB += s[n][2] + s[n][3];
        }
        sumA += __shfl_xor_sync(0xffffffffu, sumA, 1);
        sumA += __shfl_xor_sync(0xffffffffu, sumA, 2);
        sumB += __shfl_xor_sync(0xffffffffu, sumB, 1);
        sumB += __shfl_xor_sync(0xffffffffu, sumB, 2);
        lA = lA * aA + sumA;
        lB = lB * aB + sumB;
        mA = mnA; mB = mnB;
#pragma unroll
        for (int n = 0; n < 8; n++) {
            o[n][0] *= aA; o[n][1] *= aA;
            o[n][2] *= aB; o[n][3] *= aB;
        }

        // ---- O += P V (bf16x3) ----
#pragma unroll
        for (int t = 0; t < 4; t++) {
            uint32_t ph[4], pl[4];
            split2(s[2 * t][0],     s[2 * t][1],     ph[0], pl[0]);
            split2(s[2 * t][2],     s[2 * t][3],     ph[1], pl[1]);
            split2(s[2 * t + 1][0], s[2 * t + 1][1], ph[2], pl[2]);
            split2(s[2 * t + 1][2], s[2 * t + 1][3], ph[3], pl[3]);
#pragma unroll
            for (int dp = 0; dp < 4; dp++) {
                const int row = t * 16 + (lid & 15);
                const int c = dp * 2 + (lid >> 4);
                const uint32_t off = fa_sw(row, c);
                uint32_t vh0, vh1, vh2, vh3, vl0, vl1, vl2, vl3;
                ldsm_x4_trans(vh0, vh1, vh2, vh3, kb + 2 * FA_TILE + off);
                ldsm_x4_trans(vl0, vl1, vl2, vl3, kb + 3 * FA_TILE + off);
                mma16816(o[2 * dp],     ph[0], ph[1], ph[2], ph[3], vh0, vh1);
                mma16816(o[2 * dp + 1], ph[0], ph[1], ph[2], ph[3], vh2, vh3);
                mma16816(o[2 * dp],     ph[0], ph[1], ph[2], ph[3], vl0, vl1);
                mma16816(o[2 * dp + 1], ph[0], ph[1], ph[2], ph[3], vl2, vl3);
                mma16816(o[2 * dp],     pl[0], pl[1], pl[2], pl[3], vh0, vh1);
                mma16816(o[2 * dp + 1], pl[0], pl[1], pl[2], pl[3], vh2, vh3);
            }
        }
        __syncthreads();
    }

    // ---- epilogue: normalize, split, write att hi/lo [B,S,D] ----
    const float invA = 1.0f / lA;
    const float invB = 1.0f / lB;
    const int b = bh >> 4;
    const int h = bh & 15;
    const int sA = qi * 64 + wid * 16 + (lid >> 2);
#pragma unroll
    for (int n = 0; n < 8; n++) {
        const int col = h * DKsz + n * 8 + 2 * (lid & 3);
        uint32_t hi0, lo0, hi1, lo1;
        split2(o[n][0] * invA, o[n][1] * invA, hi0, lo0);
        split2(o[n][2] * invB, o[n][3] * invB, hi1, lo1);
        const size_t iA = ((size_t)b * Ssz + sA) * Dsz + col;
        const size_t iB = ((size_t)b * Ssz + sA + 8) * Dsz + col;
        *(uint32_t*)&OHI[iA] = hi0;  *(uint32_t*)&OLO[iA] = lo0;
        *(uint32_t*)&OHI[iB] = hi1;  *(uint32_t*)&OLO[iB] = lo1;
    }
}

// ---------------------------------------------------------------------------
extern "C" void kernel_launch(void* const* d_in, const int* in_sizes, int n_in,
                              void* d_out, int out_size)
{
    const float* q   = (const float*)d_in[0];
    const float* k   = (const float*)d_in[1];
    const float* v   = (const float*)d_in[2];
    // d_in[3] = mask (causal, handled analytically)
    const float* w_q = (const float*)d_in[4];
    const float* b_q = (const float*)d_in[5];
    const float* w_k = (const float*)d_in[6];
    const float* b_k = (const float*)d_in[7];
    const float* w_v = (const float*)d_in[8];
    const float* b_v = (const float*)d_in[9];
    const float* w_o = (const float*)d_in[10];
    const float* b_o = (const float*)d_in[11];
    float* out = (float*)d_out;

    __nv_bfloat16 *qhi, *qlo, *khi, *klo, *vhi, *vlo;
    __nv_bfloat16 *qhh, *qhl, *khh, *khl, *vhh, *vhl, *ahi, *alo;
    __nv_bfloat16 *wqh, *wql, *wkh, *wkl, *wvh, *wvl, *woh, *wol;
    cudaGetSymbolAddress((void**)&qhi, g_q_hi);   cudaGetSymbolAddress((void**)&qlo, g_q_lo);
    cudaGetSymbolAddress((void**)&khi, g_k_hi);   cudaGetSymbolAddress((void**)&klo, g_k_lo);
    cudaGetSymbolAddress((void**)&vhi, g_v_hi);   cudaGetSymbolAddress((void**)&vlo, g_v_lo);
    cudaGetSymbolAddress((void**)&qhh, g_qh_hi);  cudaGetSymbolAddress((void**)&qhl, g_qh_lo);
    cudaGetSymbolAddress((void**)&khh, g_kh_hi);  cudaGetSymbolAddress((void**)&khl, g_kh_lo);
    cudaGetSymbolAddress((void**)&vhh, g_vh_hi);  cudaGetSymbolAddress((void**)&vhl, g_vh_lo);
    cudaGetSymbolAddress((void**)&ahi, g_att_hi); cudaGetSymbolAddress((void**)&alo, g_att_lo);
    cudaGetSymbolAddress((void**)&wqh, g_wq_hi);  cudaGetSymbolAddress((void**)&wql, g_wq_lo);
    cudaGetSymbolAddress((void**)&wkh, g_wk_hi);  cudaGetSymbolAddress((void**)&wkl, g_wk_lo);
    cudaGetSymbolAddress((void**)&wvh, g_wv_hi);  cudaGetSymbolAddress((void**)&wvl, g_wv_lo);
    cudaGetSymbolAddress((void**)&woh, g_wo_hi);  cudaGetSymbolAddress((void**)&wol, g_wo_lo);

    cudaFuncSetAttribute(gemm_tc_kernel<0>,
                         cudaFuncAttributeMaxDynamicSharedMemorySize, GEMM_SMEM);
    cudaFuncSetAttribute(gemm_tc_kernel<1>,
                         cudaFuncAttributeMaxDynamicSharedMemorySize, GEMM_SMEM);
    cudaFuncSetAttribute(flash_mma_kernel,
                         cudaFuncAttributeMaxDynamicSharedMemorySize, FA_SMEM);

    const int nAct = Mtot * Ktot;   // 4M
    const int nW   = Dsz * Dsz;     // 1M
    dim3 bSplit(256);
    dim3 gAct((nAct / 4 + 255) / 256);
    dim3 gW((nW / 4 + 255) / 256);

    split_kernel<<<gAct, bSplit>>>(q, qhi, qlo, nAct / 4);
    split_kernel<<<gAct, bSplit>>>(k, khi, klo, nAct / 4);
    split_kernel<<<gAct, bSplit>>>(v, vhi, vlo, nAct / 4);
    split_kernel<<<gW, bSplit>>>(w_q, wqh, wql, nW / 4);
    split_kernel<<<gW, bSplit>>>(w_k, wkh, wkl, nW / 4);
    split_kernel<<<gW, bSplit>>>(w_v, wvh, wvl, nW / 4);
    split_kernel<<<gW, bSplit>>>(w_o, woh, wol, nW / 4);

    dim3 gGemm(Ntot / 128, Mtot / 128);  // (8, 32)
    gemm_tc_kernel<1><<<gGemm, 256, GEMM_SMEM>>>(qhi, qlo, wqh, wql, b_q,
                                                 nullptr, qhh, qhl, 0.125f);
    gemm_tc_kernel<1><<<gGemm, 256, GEMM_SMEM>>>(khi, klo, wkh, wkl, b_k,
                                                 nullptr, khh, khl, 1.0f);
    gemm_tc_kernel<1><<<gGemm, 256, GEMM_SMEM>>>(vhi, vlo, wvh, wvl, b_v,
                                                 nullptr, vhh, vhl, 1.0f);

    dim3 gFlash(Ssz / 64, Bsz * Hsz);    // (32, 32)
    flash_mma_kernel<<<gFlash, 128, FA_SMEM>>>(qhh, qhl, khh, khl, vhh, vhl, ahi, alo);

    gemm_tc_kernel<0><<<gGemm, 256, GEMM_SMEM>>>(ahi, alo, woh, wol, b_o,
                                                 out, nullptr, nullptr, 1.0f);
}

// round 15
// speedup vs baseline: 1.1458x; 1.0593x over previous
#include <cuda_runtime.h>
#include <cuda_bf16.h>
#include <math.h>
#include <stdint.h>

// Problem constants
#define Bsz  2
#define Ssz  2048
#define Dsz  1024
#define Hsz  16
#define DKsz 64
#define Mtot (Bsz * Ssz)   // 4096
#define Ntot Dsz           // 1024
#define Ktot Dsz           // 1024

// ---------------------------------------------------------------------------
// Scratch (device globals: allocation-free)
// ---------------------------------------------------------------------------
__device__ __nv_bfloat16 g_q_hi[Mtot * Ktot],  g_q_lo[Mtot * Ktot];
__device__ __nv_bfloat16 g_k_hi[Mtot * Ktot],  g_k_lo[Mtot * Ktot];
__device__ __nv_bfloat16 g_v_hi[Mtot * Ktot],  g_v_lo[Mtot * Ktot];
__device__ __nv_bfloat16 g_qh_hi[Mtot * Ktot], g_qh_lo[Mtot * Ktot];
__device__ __nv_bfloat16 g_kh_hi[Mtot * Ktot], g_kh_lo[Mtot * Ktot];
__device__ __nv_bfloat16 g_vh_hi[Mtot * Ktot], g_vh_lo[Mtot * Ktot];
__device__ __nv_bfloat16 g_att_hi[Mtot * Ktot], g_att_lo[Mtot * Ktot];
__device__ __nv_bfloat16 g_wq_hi[Dsz * Dsz], g_wq_lo[Dsz * Dsz];
__device__ __nv_bfloat16 g_wk_hi[Dsz * Dsz], g_wk_lo[Dsz * Dsz];
__device__ __nv_bfloat16 g_wv_hi[Dsz * Dsz], g_wv_lo[Dsz * Dsz];
__device__ __nv_bfloat16 g_wo_hi[Dsz * Dsz], g_wo_lo[Dsz * Dsz];

// ---------------------------------------------------------------------------
// Helpers
// ---------------------------------------------------------------------------
__device__ __forceinline__ uint32_t smem_to_u32(const void* smem_ptr) {
    uint32_t addr;
    asm("{ .reg .u64 tmp; cvta.to.shared.u64 tmp, %1; cvt.u32.u64 %0, tmp; }"
        : "=r"(addr) : "l"(smem_ptr));
    return addr;
}

__device__ __forceinline__ void cp_async16(uint32_t dst, const void* src) {
    asm volatile("cp.async.cg.shared.global [%0], [%1], 16;" :: "r"(dst), "l"(src));
}
__device__ __forceinline__ void cp_async_commit() {
    asm volatile("cp.async.commit_group;");
}
template <int N>
__device__ __forceinline__ void cp_async_wait() {
    asm volatile("cp.async.wait_group %0;" :: "n"(N));
}

__device__ __forceinline__ void ldsm_x4(uint32_t& r0, uint32_t& r1, uint32_t& r2,
                                        uint32_t& r3, uint32_t addr) {
    asm volatile("ldmatrix.sync.aligned.m8n8.x4.shared.b16 {%0,%1,%2,%3}, [%4];"
                 : "=r"(r0), "=r"(r1), "=r"(r2), "=r"(r3) : "r"(addr));
}
__device__ __forceinline__ void ldsm_x4_trans(uint32_t& r0, uint32_t& r1, uint32_t& r2,
                                              uint32_t& r3, uint32_t addr) {
    asm volatile("ldmatrix.sync.aligned.m8n8.x4.trans.shared.b16 {%0,%1,%2,%3}, [%4];"
                 : "=r"(r0), "=r"(r1), "=r"(r2), "=r"(r3) : "r"(addr));
}

__device__ __forceinline__ void mma16816(float* d,
                                         uint32_t a0, uint32_t a1, uint32_t a2, uint32_t a3,
                                         uint32_t b0, uint32_t b1) {
    asm volatile(
        "mma.sync.aligned.m16n8k16.row.col.f32.bf16.bf16.f32 "
        "{%0,%1,%2,%3}, {%4,%5,%6,%7}, {%8,%9}, {%0,%1,%2,%3};"
        : "+f"(d[0]), "+f"(d[1]), "+f"(d[2]), "+f"(d[3])
        : "r"(a0), "r"(a1), "r"(a2), "r"(a3), "r"(b0), "r"(b1));
}

__device__ __forceinline__ void split2(float x, float y, uint32_t& h, uint32_t& l) {
    __nv_bfloat162 hh = __floats2bfloat162_rn(x, y);
    float rx = x - __bfloat162float(hh.x);
    float ry = y - __bfloat162float(hh.y);
    __nv_bfloat162 ll = __floats2bfloat162_rn(rx, ry);
    h = *(uint32_t*)&hh;
    l = *(uint32_t*)&ll;
}

// ---------------------------------------------------------------------------
// Fused fp32 -> (hi, lo) split for all 7 tensors in one launch
// ---------------------------------------------------------------------------
struct SplitSegs {
    const float* src[7];
    __nv_bfloat16* hi[7];
    __nv_bfloat16* lo[7];
    int end4[7];    // cumulative float4 counts
};

__global__ void split_all_kernel(SplitSegs P)
{
    int i = blockIdx.x * blockDim.x + threadIdx.x;
    if (i >= P.end4[6]) return;
    int seg = 0;
    while (i >= P.end4[seg]) seg++;
    int base = (seg == 0) ? 0 : P.end4[seg - 1];
    int j = i - base;
    float4 v = ((const float4*)P.src[seg])[j];
    uint32_t h0, l0, h1, l1;
    split2(v.x, v.y, h0, l0);
    split2(v.z, v.w, h1, l1);
    ((uint32_t*)P.hi[seg])[j * 2 + 0] = h0;
    ((uint32_t*)P.hi[seg])[j * 2 + 1] = h1;
    ((uint32_t*)P.lo[seg])[j * 2 + 0] = l0;
    ((uint32_t*)P.lo[seg])[j * 2 + 1] = l1;
}

// ---------------------------------------------------------------------------
// bf16x3 GEMM via mma.sync: out[M,N] = A[M,K] @ B[N,K]^T + bias
// CTA 128x128, BK=32, 8 warps, 2-stage cp.async pipeline (R9 config).
// ---------------------------------------------------------------------------
#define BK 32
#define NC (Ktot / BK)                 // 32 chunks
#define TILE_B (128 * BK * 2)          // 8192 bytes per bf16 tile
#define BUF_B  (4 * TILE_B)            // Ahi, Alo, Bhi, Blo = 32 KB
#define GEMM_SMEM (2 * BUF_B)          // 64 KB

__device__ __forceinline__ uint32_t sw_off(int row, int c) {
    return (uint32_t)(row * 64 + ((c ^ ((row >> 1) & 3)) << 4));
}

__device__ __forceinline__ void prefetch_chunk(
    uint32_t sbase, int buf,
    const __nv_bfloat16* Ahi, const __nv_bfloat16* Alo,
    const __nv_bfloat16* Bhi, const __nv_bfloat16* Blo,
    int bm, int bn, int k0, int tid)
{
    const __nv_bfloat16* srcs[4] = { Ahi, Alo, Bhi, Blo };
    const int r0[4] = { bm, bm, bn, bn };
    uint32_t base = sbase + buf * BUF_B;
#pragma unroll
    for (int t = 0; t < 4; t++) {
#pragma unroll
        for (int it = 0; it < 2; it++) {
            int seg = tid + it * 256;          // 0..511
            int row = seg >> 2;                // 0..127
            int c   = seg & 3;                 // 16B chunk
            const void* src = srcs[t] + (size_t)(r0[t] + row) * Ktot + k0 + c * 8;
            cp_async16(base + t * TILE_B + sw_off(row, c), src);
        }
    }
}

// Core mainloop shared by both GEMM kernels. Accumulates into acc.
__device__ __forceinline__ void gemm_mainloop(
    uint32_t sbase, int bm, int bn, int tid, int wr, int wc, int lid,
    const __nv_bfloat16* Ahi, const __nv_bfloat16* Alo,
    const __nv_bfloat16* Bhi, const __nv_bfloat16* Blo,
    float acc[4][4][4])
{
    prefetch_chunk(sbase, 0, Ahi, Alo, Bhi, Blo, bm, bn, 0, tid);
    cp_async_commit();

    for (int c = 0; c < NC; c++) {
        if (c + 1 < NC) {
            prefetch_chunk(sbase, (c + 1) & 1, Ahi, Alo, Bhi, Blo,
                           bm, bn, (c + 1) * BK, tid);
            cp_async_commit();
            cp_async_wait<1>();
        } else {
            cp_async_wait<0>();
        }
        __syncthreads();

        const uint32_t buf = sbase + (c & 1) * BUF_B;
        const uint32_t sAhi = buf + 0 * TILE_B;
        const uint32_t sAlo = buf + 1 * TILE_B;
        const uint32_t sBhi = buf + 2 * TILE_B;
        const uint32_t sBlo = buf + 3 * TILE_B;

#pragma unroll
        for (int ks = 0; ks < 2; ks++) {
            uint32_t bh[4][2], bl[4][2];
#pragma unroll
            for (int p = 0; p < 2; p++) {
                const int nrow = wc * 32 + p * 16 + (lid & 15);
                const int kc = ks * 2 + (lid >> 4);
                uint32_t r0, r1, r2, r3;
                ldsm_x4(r0, r1, r2, r3, sBhi + sw_off(nrow, kc));
                bh[p * 2][0] = r0; bh[p * 2 + 1][0] = r1;
                bh[p * 2][1] = r2; bh[p * 2 + 1][1] = r3;
                ldsm_x4(r0, r1, r2, r3, sBlo + sw_off(nrow, kc));
                bl[p * 2][0] = r0; bl[p * 2 + 1][0] = r1;
                bl[p * 2][1] = r2; bl[p * 2 + 1][1] = r3;
            }
#pragma unroll
            for (int mi = 0; mi < 4; mi++) {
                const int mrow = wr * 64 + mi * 16 + (lid & 15);
                const int kc = ks * 2 + (lid >> 4);
                uint32_t ah0, ah1, ah2, ah3, al0, al1, al2, al3;
                ldsm_x4(ah0, ah1, ah2, ah3, sAhi + sw_off(mrow, kc));
                ldsm_x4(al0, al1, al2, al3, sAlo + sw_off(mrow, kc));
#pragma unroll
                for (int ni = 0; ni < 4; ni++) {
                    float* d = acc[mi][ni];
                    mma16816(d, ah0, ah1, ah2, ah3, bh[ni][0], bh[ni][1]);
                    mma16816(d, ah0, ah1, ah2, ah3, bl[ni][0], bl[ni][1]);
                    mma16816(d, al0, al1, al2, al3, bh[ni][0], bh[ni][1]);
                }
            }
        }
        __syncthreads();
    }
}

// Fused QKV projection: gridDim.z selects {Q,K,V}; bf16 hi/lo head-scatter out.
struct QKVParams {
    const __nv_bfloat16* Ahi[3];
    const __nv_bfloat16* Alo[3];
    const __nv_bfloat16* Bhi[3];
    const __nv_bfloat16* Blo[3];
    const float* bias[3];
    __nv_bfloat16* outH[3];
    __nv_bfloat16* outL[3];
    float scale[3];
};

__global__ __launch_bounds__(256, 2) void qkv_gemm_kernel(QKVParams P)
{
    extern __shared__ __align__(128) char smem[];
    const uint32_t sbase = smem_to_u32(smem);

    const int tid = threadIdx.x;
    const int wid = tid >> 5;
    const int lid = tid & 31;
    const int wr = wid >> 2;
    const int wc = wid & 3;
    const int bm = blockIdx.y * 128;
    const int bn = blockIdx.x * 128;
    const int z  = blockIdx.z;

    float acc[4][4][4];
#pragma unroll
    for (int mi = 0; mi < 4; mi++)
#pragma unroll
        for (int ni = 0; ni < 4; ni++)
#pragma unroll
            for (int r = 0; r < 4; r++) acc[mi][ni][r] = 0.0f;

    gemm_mainloop(sbase, bm, bn, tid, wr, wc, lid,
                  P.Ahi[z], P.Alo[z], P.Bhi[z], P.Blo[z], acc);

    const float scale = P.scale[z];
    const float* bias = P.bias[z];
    __nv_bfloat16* outH = P.outH[z];
    __nv_bfloat16* outL = P.outL[z];

#pragma unroll
    for (int mi = 0; mi < 4; mi++) {
#pragma unroll
        for (int ni = 0; ni < 4; ni++) {
#pragma unroll
            for (int half = 0; half < 2; half++) {
                const int m = bm + wr * 64 + mi * 16 + (lid >> 2) + half * 8;
                const int n = bn + wc * 32 + ni * 8 + 2 * (lid & 3);
                float v0 = (acc[mi][ni][half * 2 + 0] + bias[n]) * scale;
                float v1 = (acc[mi][ni][half * 2 + 1] + bias[n + 1]) * scale;
                uint32_t h, l;
                split2(v0, v1, h, l);
                const int b  = m >> 11;
                const int s  = m & 2047;
                const int hh = n >> 6;
                const int dk = n & 63;
                const size_t idx = (((size_t)(b * Hsz + hh) * Ssz) + s) * DKsz + dk;
                *(uint32_t*)&outH[idx] = h;
                *(uint32_t*)&outL[idx] = l;
            }
        }
    }
}

// Output projection: fp32 [M,N] out.
__global__ __launch_bounds__(256, 2) void oproj_gemm_kernel(
    const __nv_bfloat16* __restrict__ Ahi, const __nv_bfloat16* __restrict__ Alo,
    const __nv_bfloat16* __restrict__ Bhi, const __nv_bfloat16* __restrict__ Blo,
    const float* __restrict__ bias, float* __restrict__ outF)
{
    extern __shared__ __align__(128) char smem[];
    const uint32_t sbase = smem_to_u32(smem);

    const int tid = threadIdx.x;
    const int wid = tid >> 5;
    const int lid = tid & 31;
    const int wr = wid >> 2;
    const int wc = wid & 3;
    const int bm = blockIdx.y * 128;
    const int bn = blockIdx.x * 128;

    float acc[4][4][4];
#pragma unroll
    for (int mi = 0; mi < 4; mi++)
#pragma unroll
        for (int ni = 0; ni < 4; ni++)
#pragma unroll
            for (int r = 0; r < 4; r++) acc[mi][ni][r] = 0.0f;

    gemm_mainloop(sbase, bm, bn, tid, wr, wc, lid, Ahi, Alo, Bhi, Blo, acc);

#pragma unroll
    for (int mi = 0; mi < 4; mi++) {
#pragma unroll
        for (int ni = 0; ni < 4; ni++) {
#pragma unroll
            for (int half = 0; half < 2; half++) {
                const int m = bm + wr * 64 + mi * 16 + (lid >> 2) + half * 8;
                const int n = bn + wc * 32 + ni * 8 + 2 * (lid & 3);
                const float v0 = acc[mi][ni][half * 2 + 0] + bias[n];
                const float v1 = acc[mi][ni][half * 2 + 1] + bias[n + 1];
                *(float2*)&outF[(size_t)m * Ntot + n] = make_float2(v0, v1);
            }
        }
    }
}

// ---------------------------------------------------------------------------
// Flash attention via mma.sync bf16x3. Causal.  (R9 config: 128 thr, BQ=64)
// ---------------------------------------------------------------------------
#define FA_TILE 8192
#define FA_KVBUF (4 * FA_TILE)
#define FA_SMEM (2 * FA_TILE + 2 * FA_KVBUF)   // 80 KB

__device__ __forceinline__ uint32_t fa_sw(int row, int c) {
    return (uint32_t)(row * 128 + ((c ^ (row & 7)) << 4));
}

__device__ __forceinline__ void fa_prefetch_kv(
    uint32_t dstbase,
    const __nv_bfloat16* KH, const __nv_bfloat16* KL,
    const __nv_bfloat16* VH, const __nv_bfloat16* VL,
    size_t gbase, int tid)
{
    const __nv_bfloat16* srcs[4] = { KH, KL, VH, VL };
#pragma unroll
    for (int t = 0; t < 4; t++) {
#pragma unroll
        for (int it = 0; it < 4; it++) {
            int seg = tid + it * 128;
            int row = seg >> 3;
            int c   = seg & 7;
            cp_async16(dstbase + t * FA_TILE + fa_sw(row, c),
                       srcs[t] + gbase + (size_t)row * DKsz + c * 8);
        }
    }
}

__global__ __launch_bounds__(128, 2) void flash_mma_kernel(
    const __nv_bfloat16* __restrict__ QHI, const __nv_bfloat16* __restrict__ QLO,
    const __nv_bfloat16* __restrict__ KHI, const __nv_bfloat16* __restrict__ KLO,
    const __nv_bfloat16* __restrict__ VHI, const __nv_bfloat16* __restrict__ VLO,
    __nv_bfloat16* __restrict__ OHI, __nv_bfloat16* __restrict__ OLO)
{
    extern __shared__ __align__(128) char smem[];
    const uint32_t sb = smem_to_u32(smem);
    const int tid = threadIdx.x;
    const int wid = tid >> 5;
    const int lid = tid & 31;
    const int qi = gridDim.x - 1 - blockIdx.x;   // heavy tiles first
    const int bh = blockIdx.y;

    const size_t qbase = ((size_t)bh * Ssz + qi * 64) * DKsz;
    {
        const __nv_bfloat16* srcs[2] = { QHI, QLO };
#pragma unroll
        for (int t = 0; t < 2; t++) {
#pragma unroll
            for (int it = 0; it < 4; it++) {
                int seg = tid + it * 128;
                int row = seg >> 3;
                int c   = seg & 7;
                cp_async16(sb + t * FA_TILE + fa_sw(row, c),
                           srcs[t] + qbase + (size_t)row * DKsz + c * 8);
            }
        }
    }
    cp_async_commit();
    const uint32_t kvbase = sb + 2 * FA_TILE;
    fa_prefetch_kv(kvbase, KHI, KLO, VHI, VLO, ((size_t)bh * Ssz) * DKsz, tid);
    cp_async_commit();
    cp_async_wait<0>();
    __syncthreads();

    uint32_t qfh[4][4], qfl[4][4];
#pragma unroll
    for (int t = 0; t < 4; t++) {
        const int row = wid * 16 + (lid & 15);
        const int c = t * 2 + (lid >> 4);
        const uint32_t off = fa_sw(row, c);
        ldsm_x4(qfh[t][0], qfh[t][1], qfh[t][2], qfh[t][3], sb + off);
        ldsm_x4(qfl[t][0], qfl[t][1], qfl[t][2], qfl[t][3], sb + FA_TILE + off);
    }

    float o[8][4];
#pragma unroll
    for (int n = 0; n < 8; n++)
#pragma unroll
        for (int r = 0; r < 4; r++) o[n][r] = 0.0f;
    float mA = -INFINITY, mB = -INFINITY, lA = 0.0f, lB = 0.0f;

    const int rowA = qi * 64 + wid * 16 + (lid >> 2);
    const int rowB = rowA + 8;

    for (int j = 0; j <= qi; j++) {
        if (j < qi) {
            fa_prefetch_kv(kvbase + ((j + 1) & 1) * FA_KVBUF, KHI, KLO, VHI, VLO,
                           ((size_t)bh * Ssz + (j + 1) * 64) * DKsz, tid);
            cp_async_commit();
            cp_async_wait<1>();
        } else {
            cp_async_wait<0>();
        }
        __syncthreads();

        const uint32_t kb = kvbase + (j & 1) * FA_KVBUF;

        float s[8][4];
#pragma unroll
        for (int n = 0; n < 8; n++)
#pragma unroll
            for (int r = 0; r < 4; r++) s[n][r] = 0.0f;

#pragma unroll
        for (int t = 0; t < 4; t++) {
#pragma unroll
            for (int p = 0; p < 4; p++) {
                const int row = p * 16 + (lid & 15);
                const int c = t * 2 + (lid >> 4);
                const uint32_t off = fa_sw(row, c);
                uint32_t kh0, kh1, kh2, kh3, kl0, kl1, kl2, kl3;
                ldsm_x4(kh0, kh1, kh2, kh3, kb + off);
                ldsm_x4(kl0, kl1, kl2, kl3, kb + FA_TILE + off);
                mma16816(s[2 * p],     qfh[t][0], qfh[t][1], qfh[t][2], qfh[t][3], kh0, kh2);
                mma16816(s[2 * p + 1], qfh[t][0], qfh[t][1], qfh[t][2], qfh[t][3], kh1, kh3);
                mma16816(s[2 * p],     qfh[t][0], qfh[t][1], qfh[t][2], qfh[t][3], kl0, kl2);
                mma16816(s[2 * p + 1], qfh[t][0], qfh[t][1], qfh[t][2], qfh[t][3], kl1, kl3);
                mma16816(s[2 * p],     qfl[t][0], qfl[t][1], qfl[t][2], qfl[t][3], kh0, kh2);
                mma16816(s[2 * p + 1], qfl[t][0], qfl[t][1], qfl[t][2], qfl[t][3], kh1, kh3);
            }
        }

        if (j == qi) {
#pragma unroll
            for (int n = 0; n < 8; n++) {
                const int col = qi * 64 + n * 8 + 2 * (lid & 3);
                if (col > rowA)     s[n][0] = -INFINITY;
                if (col + 1 > rowA) s[n][1] = -INFINITY;
                if (col > rowB)     s[n][2] = -INFINITY;
                if (col + 1 > rowB) s[n][3] = -INFINITY;
            }
        }

        float mxA = -INFINITY, mxB = -INFINITY;
#pragma unroll
        for (int n = 0; n < 8; n++) {
            mxA = fmaxf(mxA, fmaxf(s[n][0], s[n][1]));
            mxB = fmaxf(mxB, fmaxf(s[n][2], s[n][3]));
        }
        mxA = fmaxf(mxA, __shfl_xor_sync(0xffffffffu, mxA, 1));
        mxA = fmaxf(mxA, __shfl_xor_sync(0xffffffffu, mxA, 2));
        mxB = fmaxf(mxB, __shfl_xor_sync(0xffffffffu, mxB, 1));
        mxB = fmaxf(mxB, __shfl_xor_sync(0xffffffffu, mxB, 2));

        const float mnA = fmaxf(mA, mxA);
        const float mnB = fmaxf(mB, mxB);
        const float aA = __expf(mA - mnA);
        const float aB = __expf(mB - mnB);
        float sumA = 0.0f, sumB = 0.0f;
#pragma unroll
        for (int n = 0; n < 8; n++) {
            s[n][0] = __expf(s[n][0] - mnA);
            s[n][1] = __expf(s[n][1] - mnA);
            s[n][2] = __expf(s[n][2] - mnB);
            s[n][3] = __expf(s[n][3] - mnB);
            sumA += s[n][0] + s[n][1];
            sumB += s[n][2] + s[n][3];
        }
        sumA += __shfl_xor_sync(0xffffffffu, sumA, 1);
        sumA += __shfl_xor_sync(0xffffffffu, sumA, 2);
        sumB += __shfl_xor_sync(0xffffffffu, sumB, 1);
        sumB += __shfl_xor_sync(0xffffffffu, sumB, 2);
        lA = lA * aA + sumA;
        lB = lB * aB + sumB;
        mA = mnA; mB = mnB;
#pragma unroll
        for (int n = 0; n < 8; n++) {
            o[n][0] *= aA; o[n][1] *= aA;
            o[n][2] *= aB; o[n][3] *= aB;
        }

#pragma unroll
        for (int t = 0; t < 4; t++) {
            uint32_t ph[4], pl[4];
            split2(s[2 * t][0],     s[2 * t][1],     ph[0], pl[0]);
            split2(s[2 * t][2],     s[2 * t][3],     ph[1], pl[1]);
            split2(s[2 * t + 1][0], s[2 * t + 1][1], ph[2], pl[2]);
            split2(s[2 * t + 1][2], s[2 * t + 1][3], ph[3], pl[3]);
#pragma unroll
            for (int dp = 0; dp < 4; dp++) {
                const int row = t * 16 + (lid & 15);
                const int c = dp * 2 + (lid >> 4);
                const uint32_t off = fa_sw(row, c);
                uint32_t vh0, vh1, vh2, vh3, vl0, vl1, vl2, vl3;
                ldsm_x4_trans(vh0, vh1, vh2, vh3, kb + 2 * FA_TILE + off);
                ldsm_x4_trans(vl0, vl1, vl2, vl3, kb + 3 * FA_TILE + off);
                mma16816(o[2 * dp],     ph[0], ph[1], ph[2], ph[3], vh0, vh1);
                mma16816(o[2 * dp + 1], ph[0], ph[1], ph[2], ph[3], vh2, vh3);
                mma16816(o[2 * dp],     ph[0], ph[1], ph[2], ph[3], vl0, vl1);
                mma16816(o[2 * dp + 1], ph[0], ph[1], ph[2], ph[3], vl2, vl3);
                mma16816(o[2 * dp],     pl[0], pl[1], pl[2], pl[3], vh0, vh1);
                mma16816(o[2 * dp + 1], pl[0], pl[1], pl[2], pl[3], vh2, vh3);
            }
        }
        __syncthreads();
    }

    const float invA = 1.0f / lA;
    const float invB = 1.0f / lB;
    const int b = bh >> 4;
    const int h = bh & 15;
    const int sA = qi * 64 + wid * 16 + (lid >> 2);
#pragma unroll
    for (int n = 0; n < 8; n++) {
        const int col = h * DKsz + n * 8 + 2 * (lid & 3);
        uint32_t hi0, lo0, hi1, lo1;
        split2(o[n][0] * invA, o[n][1] * invA, hi0, lo0);
        split2(o[n][2] * invB, o[n][3] * invB, hi1, lo1);
        const size_t iA = ((size_t)b * Ssz + sA) * Dsz + col;
        const size_t iB = ((size_t)b * Ssz + sA + 8) * Dsz + col;
        *(uint32_t*)&OHI[iA] = hi0;  *(uint32_t*)&OLO[iA] = lo0;
        *(uint32_t*)&OHI[iB] = hi1;  *(uint32_t*)&OLO[iB] = lo1;
    }
}

// ---------------------------------------------------------------------------
extern "C" void kernel_launch(void* const* d_in, const int* in_sizes, int n_in,
                              void* d_out, int out_size)
{
    const float* q   = (const float*)d_in[0];
    const float* k   = (const float*)d_in[1];
    const float* v   = (const float*)d_in[2];
    // d_in[3] = mask (causal, handled analytically)
    const float* w_q = (const float*)d_in[4];
    const float* b_q = (const float*)d_in[5];
    const float* w_k = (const float*)d_in[6];
    const float* b_k = (const float*)d_in[7];
    const float* w_v = (const float*)d_in[8];
    const float* b_v = (const float*)d_in[9];
    const float* w_o = (const float*)d_in[10];
    const float* b_o = (const float*)d_in[11];
    float* out = (float*)d_out;

    __nv_bfloat16 *qhi, *qlo, *khi, *klo, *vhi, *vlo;
    __nv_bfloat16 *qhh, *qhl, *khh, *khl, *vhh, *vhl, *ahi, *alo;
    __nv_bfloat16 *wqh, *wql, *wkh, *wkl, *wvh, *wvl, *woh, *wol;
    cudaGetSymbolAddress((void**)&qhi, g_q_hi);   cudaGetSymbolAddress((void**)&qlo, g_q_lo);
    cudaGetSymbolAddress((void**)&khi, g_k_hi);   cudaGetSymbolAddress((void**)&klo, g_k_lo);
    cudaGetSymbolAddress((void**)&vhi, g_v_hi);   cudaGetSymbolAddress((void**)&vlo, g_v_lo);
    cudaGetSymbolAddress((void**)&qhh, g_qh_hi);  cudaGetSymbolAddress((void**)&qhl, g_qh_lo);
    cudaGetSymbolAddress((void**)&khh, g_kh_hi);  cudaGetSymbolAddress((void**)&khl, g_kh_lo);
    cudaGetSymbolAddress((void**)&vhh, g_vh_hi);  cudaGetSymbolAddress((void**)&vhl, g_vh_lo);
    cudaGetSymbolAddress((void**)&ahi, g_att_hi); cudaGetSymbolAddress((void**)&alo, g_att_lo);
    cudaGetSymbolAddress((void**)&wqh, g_wq_hi);  cudaGetSymbolAddress((void**)&wql, g_wq_lo);
    cudaGetSymbolAddress((void**)&wkh, g_wk_hi);  cudaGetSymbolAddress((void**)&wkl, g_wk_lo);
    cudaGetSymbolAddress((void**)&wvh, g_wv_hi);  cudaGetSymbolAddress((void**)&wvl, g_wv_lo);
    cudaGetSymbolAddress((void**)&woh, g_wo_hi);  cudaGetSymbolAddress((void**)&wol, g_wo_lo);

    cudaFuncSetAttribute(qkv_gemm_kernel,
                         cudaFuncAttributeMaxDynamicSharedMemorySize, GEMM_SMEM);
    cudaFuncSetAttribute(oproj_gemm_kernel,
                         cudaFuncAttributeMaxDynamicSharedMemorySize, GEMM_SMEM);
    cudaFuncSetAttribute(flash_mma_kernel,
                         cudaFuncAttributeMaxDynamicSharedMemorySize, FA_SMEM);

    // ---- fused splits ----
    const int nAct4 = (Mtot * Ktot) / 4;   // 1M float4
    const int nW4   = (Dsz * Dsz) / 4;     // 256K float4
    SplitSegs sp;
    sp.src[0] = q;   sp.hi[0] = qhi; sp.lo[0] = qlo;
    sp.src[1] = k;   sp.hi[1] = khi; sp.lo[1] = klo;
    sp.src[2] = v;   sp.hi[2] = vhi; sp.lo[2] = vlo;
    sp.src[3] = w_q; sp.hi[3] = wqh; sp.lo[3] = wql;
    sp.src[4] = w_k; sp.hi[4] = wkh; sp.lo[4] = wkl;
    sp.src[5] = w_v; sp.hi[5] = wvh; sp.lo[5] = wvl;
    sp.src[6] = w_o; sp.hi[6] = woh; sp.lo[6] = wol;
    int acc4 = 0;
    for (int i = 0; i < 7; i++) { acc4 += (i < 3) ? nAct4 : nW4; sp.end4[i] = acc4; }
    split_all_kernel<<<(acc4 + 255) / 256, 256>>>(sp);

    // ---- fused QKV projection ----
    QKVParams qp;
    qp.Ahi[0] = qhi; qp.Alo[0] = qlo; qp.Bhi[0] = wqh; qp.Blo[0] = wql;
    qp.bias[0] = b_q; qp.outH[0] = qhh; qp.outL[0] = qhl; qp.scale[0] = 0.125f;
    qp.Ahi[1] = khi; qp.Alo[1] = klo; qp.Bhi[1] = wkh; qp.Blo[1] = wkl;
    qp.bias[1] = b_k; qp.outH[1] = khh; qp.outL[1] = khl; qp.scale[1] = 1.0f;
    qp.Ahi[2] = vhi; qp.Alo[2] = vlo; qp.Bhi[2] = wvh; qp.Blo[2] = wvl;
    qp.bias[2] = b_v; qp.outH[2] = vhh; qp.outL[2] = vhl; qp.scale[2] = 1.0f;

    dim3 gQKV(Ntot / 128, Mtot / 128, 3);  // (8, 32, 3) = 768 CTAs
    qkv_gemm_kernel<<<gQKV, 256, GEMM_SMEM>>>(qp);

    // ---- flash attention ----
    dim3 gFlash(Ssz / 64, Bsz * Hsz);      // (32, 32)
    flash_mma_kernel<<<gFlash, 128, FA_SMEM>>>(qhh, qhl, khh, khl, vhh, vhl, ahi, alo);

    // ---- output projection ----
    dim3 gGemm(Ntot / 128, Mtot / 128);    // (8, 32)
    oproj_gemm_kernel<<<gGemm, 256, GEMM_SMEM>>>(ahi, alo, woh, wol, b_o, out);
}